// round 1
// baseline (speedup 1.0000x reference)
#include <cuda_runtime.h>
#include <math.h>

// ---------------- problem constants ----------------
#define N_BATCH 4
#define N_SEQ   4096
#define D_MODEL 512
#define N_HEADS 8
#define D_HEAD  64
#define M_LAND  256
#define L_POOL  16
#define N_BH    32            // N_BATCH * N_HEADS
#define N_ROWS  16384         // N_BATCH * N_SEQ
#define PINV_ITERS 6
#define K_CONV  33
#define PAD_CONV 16
#define LN_EPS  1e-5f
#define Q_SCALE 0.125f        // 64^-0.5

// ---------------- device scratch (static; allocation-free) ----------------
__device__ float g_xn  [(size_t)N_ROWS * D_MODEL];
__device__ float g_q   [(size_t)N_BH * N_SEQ * D_HEAD];
__device__ float g_k   [(size_t)N_BH * N_SEQ * D_HEAD];
__device__ float g_v   [(size_t)N_BH * N_SEQ * D_HEAD];
__device__ float g_ql  [(size_t)N_BH * M_LAND * D_HEAD];
__device__ float g_kl  [(size_t)N_BH * M_LAND * D_HEAD];
__device__ float g_kT  [(size_t)N_BH * D_HEAD * N_SEQ];
__device__ float g_klT [(size_t)N_BH * D_HEAD * M_LAND];
__device__ float g_a1  [(size_t)N_BH * N_SEQ * M_LAND];
__device__ float g_a3  [(size_t)N_BH * M_LAND * N_SEQ];
__device__ float g_a2  [(size_t)N_BH * M_LAND * M_LAND];
__device__ float g_z0  [(size_t)N_BH * M_LAND * M_LAND];
__device__ float g_z1  [(size_t)N_BH * M_LAND * M_LAND];
__device__ float g_xz  [(size_t)N_BH * M_LAND * M_LAND];
__device__ float g_w2  [(size_t)N_BH * M_LAND * M_LAND];
__device__ float g_w3  [(size_t)N_BH * M_LAND * M_LAND];
__device__ float g_a3v [(size_t)N_BH * M_LAND * D_HEAD];
__device__ float g_t1  [(size_t)N_BH * N_SEQ * M_LAND];
__device__ float g_outh[(size_t)N_BH * N_SEQ * D_HEAD];
__device__ float g_outt[(size_t)N_ROWS * D_MODEL];
__device__ unsigned int g_scal[2];

// ---------------- LayerNorm ----------------
__global__ __launch_bounds__(256) void ln_kernel(
    const float* __restrict__ x, const float* __restrict__ gamma,
    const float* __restrict__ beta, float* __restrict__ xn)
{
    int row = blockIdx.x;
    int t = threadIdx.x;
    const float* xr = x + (size_t)row * D_MODEL;
    float v0 = xr[t], v1 = xr[t + 256];
    __shared__ float ssum[256], ssq[256];
    ssum[t] = v0 + v1;
    ssq[t]  = v0 * v0 + v1 * v1;
    __syncthreads();
    for (int o = 128; o > 0; o >>= 1) {
        if (t < o) { ssum[t] += ssum[t + o]; ssq[t] += ssq[t + o]; }
        __syncthreads();
    }
    float mean = ssum[0] * (1.0f / D_MODEL);
    float var  = ssq[0] * (1.0f / D_MODEL) - mean * mean;
    float rstd = rsqrtf(var + LN_EPS);
    float* o = xn + (size_t)row * D_MODEL;
    o[t]       = (v0 - mean) * rstd * gamma[t]       + beta[t];
    o[t + 256] = (v1 - mean) * rstd * gamma[t + 256] + beta[t + 256];
}

// ---------------- generic tiled SGEMM (NN, row-major) ----------------
struct EpiStd {
    float* C; size_t cStride; int ldc;
    float c1, c2;
    const float* Add; size_t addStride;
    const float* bias;
    __device__ __forceinline__ void operator()(int z, int row, int col, float acc) const {
        float val = c1 * acc;
        if (Add)  val += c2 * Add[(size_t)z * addStride + (size_t)row * ldc + col];
        if (bias) val += bias[col];
        C[(size_t)z * cStride + (size_t)row * ldc + col] = val;
    }
};

struct EpiQKV {
    float* q; float* k; float* v;
    __device__ __forceinline__ void operator()(int z, int row, int col, float acc) const {
        (void)z;
        int which = col >> 9;
        int d = col & 511;
        int h = d >> 6, dd = d & 63;
        int b = row >> 12, n = row & 4095;
        size_t o = (((size_t)(b * N_HEADS + h)) * N_SEQ + n) * D_HEAD + dd;
        if (which == 0)      q[o] = acc * Q_SCALE;
        else if (which == 1) k[o] = acc;
        else                 v[o] = acc;
    }
};

template<int BM, int BN, int TM, int TN, class Epi>
__global__ __launch_bounds__(256) void gemm_nn(
    const float* __restrict__ A, size_t aStride, int lda,
    const float* __restrict__ B, size_t bStride, int ldb,
    int K, Epi epi)
{
    __shared__ float As[16][BM];
    __shared__ float Bs[16][BN];
    const int tid = threadIdx.x;
    const int tx = tid % (BN / TN);
    const int ty = tid / (BN / TN);
    const int z = blockIdx.z;
    const int rowBase = blockIdx.y * BM;
    const int colBase = blockIdx.x * BN;
    const float* Ab = A + (size_t)z * aStride + (size_t)rowBase * lda;
    const float* Bb = B + (size_t)z * bStride + colBase;

    float acc[TM][TN];
#pragma unroll
    for (int i = 0; i < TM; i++)
#pragma unroll
        for (int j = 0; j < TN; j++) acc[i][j] = 0.0f;

    for (int k0 = 0; k0 < K; k0 += 16) {
        for (int i = tid; i < BM * 4; i += 256) {
            int r = i >> 2, c4 = i & 3;
            float4 va = *(const float4*)&Ab[(size_t)r * lda + k0 + c4 * 4];
            As[c4 * 4 + 0][r] = va.x;
            As[c4 * 4 + 1][r] = va.y;
            As[c4 * 4 + 2][r] = va.z;
            As[c4 * 4 + 3][r] = va.w;
        }
        for (int i = tid; i < BN * 4; i += 256) {
            int r = i / (BN / 4), c4 = i % (BN / 4);
            *(float4*)&Bs[r][c4 * 4] = *(const float4*)&Bb[(size_t)(k0 + r) * ldb + c4 * 4];
        }
        __syncthreads();
#pragma unroll
        for (int kk = 0; kk < 16; kk++) {
            float ra[TM], rb[TN];
#pragma unroll
            for (int i = 0; i < TM; i += 4) {
                float4 t4 = *(const float4*)&As[kk][ty * TM + i];
                ra[i] = t4.x; ra[i + 1] = t4.y; ra[i + 2] = t4.z; ra[i + 3] = t4.w;
            }
#pragma unroll
            for (int j = 0; j < TN; j += 4) {
                float4 t4 = *(const float4*)&Bs[kk][tx * TN + j];
                rb[j] = t4.x; rb[j + 1] = t4.y; rb[j + 2] = t4.z; rb[j + 3] = t4.w;
            }
#pragma unroll
            for (int i = 0; i < TM; i++)
#pragma unroll
                for (int j = 0; j < TN; j++)
                    acc[i][j] += ra[i] * rb[j];
        }
        __syncthreads();
    }
#pragma unroll
    for (int i = 0; i < TM; i++) {
        int row = rowBase + ty * TM + i;
#pragma unroll
        for (int j = 0; j < TN; j++)
            epi(z, row, colBase + tx * TN + j, acc[i][j]);
    }
}

// ---------------- landmark pooling ----------------
__global__ __launch_bounds__(64) void landmark_kernel(
    const float* __restrict__ q, const float* __restrict__ k,
    float* __restrict__ ql, float* __restrict__ kl)
{
    int z = blockIdx.x, m = blockIdx.y, d = threadIdx.x;
    size_t inb = ((size_t)z * N_SEQ + (size_t)m * L_POOL) * D_HEAD + d;
    float sq = 0.f, sk = 0.f;
#pragma unroll
    for (int l = 0; l < L_POOL; l++) {
        sq += q[inb + (size_t)l * D_HEAD];
        sk += k[inb + (size_t)l * D_HEAD];
    }
    size_t ob = ((size_t)z * M_LAND + m) * D_HEAD + d;
    ql[ob] = sq * (1.0f / L_POOL);
    kl[ob] = sk * (1.0f / L_POOL);
}

// ---------------- transpose [R,64] -> [64,R], batched ----------------
__global__ void transpose64_kernel(const float* __restrict__ src,
                                   float* __restrict__ dst, int R)
{
    __shared__ float tile[32][33];
    int z = blockIdx.z;
    int r0 = blockIdx.x * 32, c0 = blockIdx.y * 32;
    const float* s = src + (size_t)z * R * 64;
    float* d = dst + (size_t)z * 64 * R;
    tile[threadIdx.y][threadIdx.x] = s[(size_t)(r0 + threadIdx.y) * 64 + c0 + threadIdx.x];
    __syncthreads();
    d[(size_t)(c0 + threadIdx.y) * R + r0 + threadIdx.x] = tile[threadIdx.x][threadIdx.y];
}

// ---------------- row softmax (in-place) ----------------
__global__ __launch_bounds__(256) void softmax_kernel(float* __restrict__ data, int W)
{
    size_t base = (size_t)blockIdx.x * W;
    int t = threadIdx.x;
    __shared__ float sh[256];
    float m = -INFINITY;
    for (int i = t; i < W; i += 256) m = fmaxf(m, data[base + i]);
    sh[t] = m; __syncthreads();
    for (int o = 128; o > 0; o >>= 1) {
        if (t < o) sh[t] = fmaxf(sh[t], sh[t + o]);
        __syncthreads();
    }
    float rowmax = sh[0];
    __syncthreads();
    float s = 0.f;
    for (int i = t; i < W; i += 256) {
        float e = expf(data[base + i] - rowmax);
        data[base + i] = e;
        s += e;
    }
    sh[t] = s; __syncthreads();
    for (int o = 128; o > 0; o >>= 1) {
        if (t < o) sh[t] += sh[t + o];
        __syncthreads();
    }
    float inv = 1.0f / sh[0];
    __syncthreads();
    for (int i = t; i < W; i += 256) data[base + i] *= inv;
}

// ---------------- pinv scale reductions ----------------
__global__ void pinv_scale_zero(unsigned int* scal)
{
    if (threadIdx.x < 2) scal[threadIdx.x] = 0u;
}

__global__ __launch_bounds__(256) void pinv_reduce_kernel(
    const float* __restrict__ a2, unsigned int* scal)
{
    int z = blockIdx.x, t = threadIdx.x;
    const float* m = a2 + (size_t)z * M_LAND * M_LAND;
    float rowsum = 0.f, colsum = 0.f;
    for (int j = 0; j < M_LAND; j++) rowsum += fabsf(m[(size_t)t * M_LAND + j]);
    for (int i = 0; i < M_LAND; i++) colsum += fabsf(m[(size_t)i * M_LAND + t]);
    __shared__ float sh[256];
    sh[t] = rowsum; __syncthreads();
    for (int o = 128; o > 0; o >>= 1) {
        if (t < o) sh[t] = fmaxf(sh[t], sh[t + o]);
        __syncthreads();
    }
    if (t == 0) atomicMax(&scal[0], __float_as_uint(sh[0]));
    __syncthreads();
    sh[t] = colsum; __syncthreads();
    for (int o = 128; o > 0; o >>= 1) {
        if (t < o) sh[t] = fmaxf(sh[t], sh[t + o]);
        __syncthreads();
    }
    if (t == 0) atomicMax(&scal[1], __float_as_uint(sh[0]));
}

__global__ __launch_bounds__(256) void z_init_kernel(
    const float* __restrict__ a2, const unsigned int* __restrict__ scal,
    float* __restrict__ z0)
{
    int z = blockIdx.x, i = blockIdx.y, j = threadIdx.x;
    float inv = 1.0f / (__uint_as_float(scal[0]) * __uint_as_float(scal[1]));
    z0[((size_t)z * M_LAND + j) * M_LAND + i] =
        a2[((size_t)z * M_LAND + i) * M_LAND + j] * inv;
}

// ---------------- depthwise conv residual (adds into outh) ----------------
__global__ __launch_bounds__(256) void conv_res_kernel(
    const float* __restrict__ v, const float* __restrict__ rw,
    float* __restrict__ outh)
{
    __shared__ float sv[96][64];
    __shared__ float w[K_CONV];
    int z = blockIdx.x, h = z & 7;
    int n0 = blockIdx.y * 64;
    int t = threadIdx.x;
    if (t < K_CONV) w[t] = rw[h * K_CONV + t];
    const float* vb = v + (size_t)z * N_SEQ * D_HEAD;
    for (int i = t; i < 96 * 64; i += 256) {
        int r = i >> 6, c = i & 63;
        int n = n0 - PAD_CONV + r;
        sv[r][c] = (n >= 0 && n < N_SEQ) ? vb[(size_t)n * D_HEAD + c] : 0.0f;
    }
    __syncthreads();
    int d = t & 63, r0 = t >> 6;
    for (int rr = r0; rr < 64; rr += 4) {
        float acc = 0.f;
#pragma unroll
        for (int kk = 0; kk < K_CONV; kk++) acc += w[kk] * sv[rr + kk][d];
        outh[(size_t)z * N_SEQ * D_HEAD + (size_t)(n0 + rr) * D_HEAD + d] += acc;
    }
}

// ---------------- merge heads: [b,h,n,dh] -> [b,n,h*dh] ----------------
__global__ __launch_bounds__(256) void merge_heads_kernel(
    const float* __restrict__ outh, float* __restrict__ outt)
{
    size_t idx = (size_t)blockIdx.x * 256 + threadIdx.x;
    int dd = (int)(idx & 63);
    size_t r = idx >> 6;
    int n = (int)(r & 4095);
    int z = (int)(r >> 12);
    int b = z >> 3, h = z & 7;
    outt[((size_t)(b * N_SEQ + n)) * D_MODEL + h * D_HEAD + dd] = outh[idx];
}

// ---------------- host launch ----------------
extern "C" void kernel_launch(void* const* d_in, const int* in_sizes, int n_in,
                              void* d_out, int out_size)
{
    (void)in_sizes; (void)n_in; (void)out_size;
    const float* x     = (const float*)d_in[0];
    const float* gamma = (const float*)d_in[1];
    const float* beta  = (const float*)d_in[2];
    const float* w_qkv = (const float*)d_in[3];
    const float* w_out = (const float*)d_in[4];
    const float* b_out = (const float*)d_in[5];
    const float* res_w = (const float*)d_in[6];
    float* out = (float*)d_out;

    float *xn, *q, *k, *v, *ql, *kl, *kT, *klT, *a1, *a3, *a2;
    float *z0, *z1, *xz, *w2, *w3, *a3v, *t1, *outh, *outt;
    unsigned int* scal;
    cudaGetSymbolAddress((void**)&xn,  g_xn);
    cudaGetSymbolAddress((void**)&q,   g_q);
    cudaGetSymbolAddress((void**)&k,   g_k);
    cudaGetSymbolAddress((void**)&v,   g_v);
    cudaGetSymbolAddress((void**)&ql,  g_ql);
    cudaGetSymbolAddress((void**)&kl,  g_kl);
    cudaGetSymbolAddress((void**)&kT,  g_kT);
    cudaGetSymbolAddress((void**)&klT, g_klT);
    cudaGetSymbolAddress((void**)&a1,  g_a1);
    cudaGetSymbolAddress((void**)&a3,  g_a3);
    cudaGetSymbolAddress((void**)&a2,  g_a2);
    cudaGetSymbolAddress((void**)&z0,  g_z0);
    cudaGetSymbolAddress((void**)&z1,  g_z1);
    cudaGetSymbolAddress((void**)&xz,  g_xz);
    cudaGetSymbolAddress((void**)&w2,  g_w2);
    cudaGetSymbolAddress((void**)&w3,  g_w3);
    cudaGetSymbolAddress((void**)&a3v, g_a3v);
    cudaGetSymbolAddress((void**)&t1,  g_t1);
    cudaGetSymbolAddress((void**)&outh, g_outh);
    cudaGetSymbolAddress((void**)&outt, g_outt);
    cudaGetSymbolAddress((void**)&scal, g_scal);

    const size_t SZ2 = (size_t)M_LAND * M_LAND;

    // 1. LayerNorm
    ln_kernel<<<N_ROWS, 256>>>(x, gamma, beta, xn);

    // 2. QKV GEMM with scatter-to-heads epilogue (q scaled)
    {
        EpiQKV e{q, k, v};
        gemm_nn<128, 128, 8, 8, EpiQKV><<<dim3(1536 / 128, N_ROWS / 128, 1), 256>>>(
            xn, 0, D_MODEL, w_qkv, 0, 3 * D_MODEL, D_MODEL, e);
    }

    // 3. landmark pooling
    landmark_kernel<<<dim3(N_BH, M_LAND), 64>>>(q, k, ql, kl);

    // 4. transposes so sims are NN GEMMs
    transpose64_kernel<<<dim3(N_SEQ / 32, 2, N_BH), dim3(32, 32)>>>(k, kT, N_SEQ);
    transpose64_kernel<<<dim3(M_LAND / 32, 2, N_BH), dim3(32, 32)>>>(kl, klT, M_LAND);

    // 5. similarity GEMMs
    {   // sim1 = q @ k_l^T   [bh, 4096, 256]
        EpiStd e{a1, (size_t)N_SEQ * M_LAND, M_LAND, 1.f, 0.f, nullptr, 0, nullptr};
        gemm_nn<128, 128, 8, 8, EpiStd><<<dim3(M_LAND / 128, N_SEQ / 128, N_BH), 256>>>(
            q, (size_t)N_SEQ * D_HEAD, D_HEAD, klT, (size_t)D_HEAD * M_LAND, M_LAND, D_HEAD, e);
    }
    {   // sim2 = q_l @ k_l^T [bh, 256, 256]
        EpiStd e{a2, SZ2, M_LAND, 1.f, 0.f, nullptr, 0, nullptr};
        gemm_nn<128, 128, 8, 8, EpiStd><<<dim3(2, 2, N_BH), 256>>>(
            ql, (size_t)M_LAND * D_HEAD, D_HEAD, klT, (size_t)D_HEAD * M_LAND, M_LAND, D_HEAD, e);
    }
    {   // sim3 = q_l @ k^T   [bh, 256, 4096]
        EpiStd e{a3, (size_t)M_LAND * N_SEQ, N_SEQ, 1.f, 0.f, nullptr, 0, nullptr};
        gemm_nn<128, 128, 8, 8, EpiStd><<<dim3(N_SEQ / 128, 2, N_BH), 256>>>(
            ql, (size_t)M_LAND * D_HEAD, D_HEAD, kT, (size_t)D_HEAD * N_SEQ, N_SEQ, D_HEAD, e);
    }

    // 6. softmaxes (in place)
    softmax_kernel<<<N_BH * N_SEQ, 256>>>(a1, M_LAND);
    softmax_kernel<<<N_BH * M_LAND, 256>>>(a2, M_LAND);
    softmax_kernel<<<N_BH * M_LAND, 256>>>(a3, N_SEQ);

    // 7. pinv init: z0 = a2^T / (max(rowsums) * max(colsums))  (global maxes)
    pinv_scale_zero<<<1, 32>>>(scal);
    pinv_reduce_kernel<<<N_BH, 256>>>(a2, scal);
    z_init_kernel<<<dim3(N_BH, M_LAND), 256>>>(a2, scal, z0);

    // 8. Newton-Schulz iterations (pure GEMMs with fused epilogues)
    float* zc = z0;
    float* zn = z1;
    for (int it = 0; it < PINV_ITERS; it++) {
        {   // xz = a2 @ z
            EpiStd e{xz, SZ2, M_LAND, 1.f, 0.f, nullptr, 0, nullptr};
            gemm_nn<128, 128, 8, 8, EpiStd><<<dim3(2, 2, N_BH), 256>>>(
                a2, SZ2, M_LAND, zc, SZ2, M_LAND, M_LAND, e);
        }
        {   // w2 = xz @ (7I - xz) = 7*xz - xz@xz
            EpiStd e{w2, SZ2, M_LAND, -1.f, 7.f, xz, SZ2, nullptr};
            gemm_nn<128, 128, 8, 8, EpiStd><<<dim3(2, 2, N_BH), 256>>>(
                xz, SZ2, M_LAND, xz, SZ2, M_LAND, M_LAND, e);
        }
        {   // w3 = xz @ (15I - w2) = 15*xz - xz@w2
            EpiStd e{w3, SZ2, M_LAND, -1.f, 15.f, xz, SZ2, nullptr};
            gemm_nn<128, 128, 8, 8, EpiStd><<<dim3(2, 2, N_BH), 256>>>(
                xz, SZ2, M_LAND, w2, SZ2, M_LAND, M_LAND, e);
        }
        {   // z' = 0.25 * z @ (13I - w3) = 3.25*z - 0.25*z@w3
            EpiStd e{zn, SZ2, M_LAND, -0.25f, 3.25f, zc, SZ2, nullptr};
            gemm_nn<128, 128, 8, 8, EpiStd><<<dim3(2, 2, N_BH), 256>>>(
                zc, SZ2, M_LAND, w3, SZ2, M_LAND, M_LAND, e);
        }
        float* tswap = zc; zc = zn; zn = tswap;
    }

    // 9. a3v = a3 @ v   [bh, 256, 64]
    {
        EpiStd e{a3v, (size_t)M_LAND * D_HEAD, D_HEAD, 1.f, 0.f, nullptr, 0, nullptr};
        gemm_nn<128, 64, 8, 4, EpiStd><<<dim3(1, 2, N_BH), 256>>>(
            a3, (size_t)M_LAND * N_SEQ, N_SEQ, v, (size_t)N_SEQ * D_HEAD, D_HEAD, N_SEQ, e);
    }
    // 10. t1 = a1 @ z_final  [bh, 4096, 256]
    {
        EpiStd e{t1, (size_t)N_SEQ * M_LAND, M_LAND, 1.f, 0.f, nullptr, 0, nullptr};
        gemm_nn<128, 128, 8, 8, EpiStd><<<dim3(2, N_SEQ / 128, N_BH), 256>>>(
            a1, (size_t)N_SEQ * M_LAND, M_LAND, zc, SZ2, M_LAND, M_LAND, e);
    }
    // 11. outh = t1 @ a3v  [bh, 4096, 64]
    {
        EpiStd e{outh, (size_t)N_SEQ * D_HEAD, D_HEAD, 1.f, 0.f, nullptr, 0, nullptr};
        gemm_nn<128, 64, 8, 4, EpiStd><<<dim3(1, N_SEQ / 128, N_BH), 256>>>(
            t1, (size_t)N_SEQ * M_LAND, M_LAND, a3v, (size_t)M_LAND * D_HEAD, D_HEAD, M_LAND, e);
    }

    // 12. depthwise conv residual (adds into outh)
    conv_res_kernel<<<dim3(N_BH, N_SEQ / 64), 256>>>(v, res_w, outh);

    // 13. merge heads
    merge_heads_kernel<<<((size_t)N_ROWS * D_MODEL) / 256, 256>>>(outh, outt);

    // 14. final GEMM: out = x + outt @ w_out + b_out
    {
        EpiStd e{out, 0, D_MODEL, 1.f, 1.f, x, 0, b_out};
        gemm_nn<128, 128, 8, 8, EpiStd><<<dim3(D_MODEL / 128, N_ROWS / 128, 1), 256>>>(
            outt, 0, D_MODEL, w_out, 0, D_MODEL, D_MODEL, e);
    }
}

// round 2
// speedup vs baseline: 2.3816x; 2.3816x over previous
#include <cuda_runtime.h>
#include <math.h>
#include <stdint.h>

// ---------------- problem constants ----------------
#define N_BATCH 4
#define N_SEQ   4096
#define D_MODEL 512
#define N_HEADS 8
#define D_HEAD  64
#define M_LAND  256
#define L_POOL  16
#define N_BH    32            // N_BATCH * N_HEADS
#define N_ROWS  16384         // N_BATCH * N_SEQ
#define PINV_ITERS 6
#define K_CONV  33
#define PAD_CONV 16
#define LN_EPS  1e-5f
#define Q_SCALE 0.125f        // 64^-0.5

// ---------------- device scratch (static; allocation-free) ----------------
__device__ float g_xn  [(size_t)N_ROWS * D_MODEL];
__device__ float g_q   [(size_t)N_BH * N_SEQ * D_HEAD];
__device__ float g_k   [(size_t)N_BH * N_SEQ * D_HEAD];
__device__ float g_v   [(size_t)N_BH * N_SEQ * D_HEAD];
__device__ float g_ql  [(size_t)N_BH * M_LAND * D_HEAD];
__device__ float g_kl  [(size_t)N_BH * M_LAND * D_HEAD];
__device__ float g_kT  [(size_t)N_BH * D_HEAD * N_SEQ];
__device__ float g_klT [(size_t)N_BH * D_HEAD * M_LAND];
__device__ float g_a1  [(size_t)N_BH * N_SEQ * M_LAND];
__device__ float g_a3  [(size_t)N_BH * M_LAND * N_SEQ];
__device__ float g_a2  [(size_t)N_BH * M_LAND * M_LAND];
__device__ float g_z0  [(size_t)N_BH * M_LAND * M_LAND];
__device__ float g_z1  [(size_t)N_BH * M_LAND * M_LAND];
__device__ float g_xz  [(size_t)N_BH * M_LAND * M_LAND];
__device__ float g_w2  [(size_t)N_BH * M_LAND * M_LAND];
__device__ float g_w3  [(size_t)N_BH * M_LAND * M_LAND];
__device__ float g_a3v [(size_t)N_BH * M_LAND * D_HEAD];
__device__ float g_t1  [(size_t)N_BH * N_SEQ * M_LAND];
__device__ float g_outh[(size_t)N_BH * N_SEQ * D_HEAD];
__device__ float g_outt[(size_t)N_ROWS * D_MODEL];
__device__ unsigned int g_scal[2];

// ---------------- tf32 helpers ----------------
__device__ __forceinline__ float tf32r(float x) {
    uint32_t u;
    asm("cvt.rna.tf32.f32 %0, %1;" : "=r"(u) : "f"(x));
    return __uint_as_float(u);
}

__device__ __forceinline__ void mma_tf32(float* d, const uint32_t* a, const uint32_t* b) {
    asm volatile(
        "mma.sync.aligned.m16n8k8.row.col.f32.tf32.tf32.f32 "
        "{%0,%1,%2,%3}, {%4,%5,%6,%7}, {%8,%9}, {%0,%1,%2,%3};\n"
        : "+f"(d[0]), "+f"(d[1]), "+f"(d[2]), "+f"(d[3])
        : "r"(a[0]), "r"(a[1]), "r"(a[2]), "r"(a[3]), "r"(b[0]), "r"(b[1]));
}

// ---------------- LayerNorm ----------------
__global__ __launch_bounds__(256) void ln_kernel(
    const float* __restrict__ x, const float* __restrict__ gamma,
    const float* __restrict__ beta, float* __restrict__ xn)
{
    int row = blockIdx.x;
    int t = threadIdx.x;
    const float* xr = x + (size_t)row * D_MODEL;
    float v0 = xr[t], v1 = xr[t + 256];
    __shared__ float ssum[256], ssq[256];
    ssum[t] = v0 + v1;
    ssq[t]  = v0 * v0 + v1 * v1;
    __syncthreads();
    for (int o = 128; o > 0; o >>= 1) {
        if (t < o) { ssum[t] += ssum[t + o]; ssq[t] += ssq[t + o]; }
        __syncthreads();
    }
    float mean = ssum[0] * (1.0f / D_MODEL);
    float var  = ssq[0] * (1.0f / D_MODEL) - mean * mean;
    float rstd = rsqrtf(var + LN_EPS);
    float* o = xn + (size_t)row * D_MODEL;
    o[t]       = (v0 - mean) * rstd * gamma[t]       + beta[t];
    o[t + 256] = (v1 - mean) * rstd * gamma[t + 256] + beta[t + 256];
}

// ---------------- epilogue functors ----------------
struct EpiStd {
    float* C; size_t cStride; int ldc;
    float c1, c2;
    const float* Add; size_t addStride;
    const float* bias;
    __device__ __forceinline__ void operator()(int z, int row, int col, float acc) const {
        float val = c1 * acc;
        if (Add)  val += c2 * Add[(size_t)z * addStride + (size_t)row * ldc + col];
        if (bias) val += bias[col];
        C[(size_t)z * cStride + (size_t)row * ldc + col] = val;
    }
};

struct EpiQKV {
    float* q; float* k; float* v;
    __device__ __forceinline__ void operator()(int z, int row, int col, float acc) const {
        (void)z;
        int which = col >> 9;
        int d = col & 511;
        int h = d >> 6, dd = d & 63;
        int b = row >> 12, n = row & 4095;
        size_t o = (((size_t)(b * N_HEADS + h)) * N_SEQ + n) * D_HEAD + dd;
        if (which == 0)      q[o] = acc * Q_SCALE;
        else if (which == 1) k[o] = acc;
        else                 v[o] = acc;
    }
};

// ---------------- tf32 tensor-core GEMM (NN, row-major) ----------------
// BM x BN block tile, BK=32 chunks, 8 warps of warp-tile WM x WN.
// A staged row-major [BM][36] (pad 4: frag banks 4g+t4 distinct, float4-aligned).
// B staged k-major  [32][BN+8] (stride mod 32 == 8: frag banks 8t4+g distinct).
template<int BM, int BN, int WM, int WN, class Epi>
__global__ __launch_bounds__(256) void gemm_tf32(
    const float* __restrict__ A, size_t aStride, int lda,
    const float* __restrict__ B, size_t bStride, int ldb,
    int K, Epi epi)
{
    constexpr int WARPS_M = BM / WM;
    constexpr int WARPS_N = BN / WN;
    static_assert(WARPS_M * WARPS_N == 8, "need 8 warps");
    constexpr int MT  = WM / 16;
    constexpr int NTL = WN / 8;
    constexpr int AP  = 36;
    constexpr int BNP = BN + 8;

    __shared__ float As[BM][AP];
    __shared__ float Bs[32][BNP];

    const int tid  = threadIdx.x;
    const int lane = tid & 31;
    const int warp = tid >> 5;
    const int wm = warp % WARPS_M;
    const int wn = warp / WARPS_M;
    const int g  = lane >> 2;
    const int t4 = lane & 3;
    const int z  = blockIdx.z;
    const int rowBase = blockIdx.y * BM;
    const int colBase = blockIdx.x * BN;
    const float* Ab = A + (size_t)z * aStride + (size_t)rowBase * lda;
    const float* Bb = B + (size_t)z * bStride + colBase;

    float acc[MT][NTL][4];
#pragma unroll
    for (int i = 0; i < MT; i++)
#pragma unroll
        for (int j = 0; j < NTL; j++) {
            acc[i][j][0] = 0.f; acc[i][j][1] = 0.f;
            acc[i][j][2] = 0.f; acc[i][j][3] = 0.f;
        }

    for (int k0 = 0; k0 < K; k0 += 32) {
        // stage A: BM rows x 32 k (converted to tf32 once here)
#pragma unroll
        for (int i = tid; i < BM * 8; i += 256) {
            int r = i >> 3, c4 = (i & 7) << 2;
            float4 va = *(const float4*)&Ab[(size_t)r * lda + k0 + c4];
            float4 t;
            t.x = tf32r(va.x); t.y = tf32r(va.y);
            t.z = tf32r(va.z); t.w = tf32r(va.w);
            *(float4*)&As[r][c4] = t;
        }
        // stage B: 32 k rows x BN cols
#pragma unroll
        for (int i = tid; i < BN * 8; i += 256) {
            int r = i / (BN / 4), c = (i % (BN / 4)) << 2;
            float4 vb = *(const float4*)&Bb[(size_t)(k0 + r) * ldb + c];
            float4 t;
            t.x = tf32r(vb.x); t.y = tf32r(vb.y);
            t.z = tf32r(vb.z); t.w = tf32r(vb.w);
            *(float4*)&Bs[r][c] = t;
        }
        __syncthreads();

#pragma unroll
        for (int kk = 0; kk < 32; kk += 8) {
            uint32_t af[MT][4], bf[NTL][2];
#pragma unroll
            for (int mt = 0; mt < MT; mt++) {
                int r = wm * WM + mt * 16 + g;
                af[mt][0] = __float_as_uint(As[r][kk + t4]);
                af[mt][1] = __float_as_uint(As[r + 8][kk + t4]);
                af[mt][2] = __float_as_uint(As[r][kk + t4 + 4]);
                af[mt][3] = __float_as_uint(As[r + 8][kk + t4 + 4]);
            }
#pragma unroll
            for (int nt = 0; nt < NTL; nt++) {
                int c = wn * WN + nt * 8 + g;
                bf[nt][0] = __float_as_uint(Bs[kk + t4][c]);
                bf[nt][1] = __float_as_uint(Bs[kk + t4 + 4][c]);
            }
#pragma unroll
            for (int mt = 0; mt < MT; mt++)
#pragma unroll
                for (int nt = 0; nt < NTL; nt++)
                    mma_tf32(acc[mt][nt], af[mt], bf[nt]);
        }
        __syncthreads();
    }

    // epilogue: c0,c1 at (row, 2*t4 | +1), c2,c3 at (row+8, same cols)
#pragma unroll
    for (int mt = 0; mt < MT; mt++) {
        int row0 = rowBase + wm * WM + mt * 16 + g;
#pragma unroll
        for (int nt = 0; nt < NTL; nt++) {
            int col = colBase + wn * WN + nt * 8 + t4 * 2;
            epi(z, row0,     col,     acc[mt][nt][0]);
            epi(z, row0,     col + 1, acc[mt][nt][1]);
            epi(z, row0 + 8, col,     acc[mt][nt][2]);
            epi(z, row0 + 8, col + 1, acc[mt][nt][3]);
        }
    }
}

// ---------------- landmark pooling ----------------
__global__ __launch_bounds__(64) void landmark_kernel(
    const float* __restrict__ q, const float* __restrict__ k,
    float* __restrict__ ql, float* __restrict__ kl)
{
    int z = blockIdx.x, m = blockIdx.y, d = threadIdx.x;
    size_t inb = ((size_t)z * N_SEQ + (size_t)m * L_POOL) * D_HEAD + d;
    float sq = 0.f, sk = 0.f;
#pragma unroll
    for (int l = 0; l < L_POOL; l++) {
        sq += q[inb + (size_t)l * D_HEAD];
        sk += k[inb + (size_t)l * D_HEAD];
    }
    size_t ob = ((size_t)z * M_LAND + m) * D_HEAD + d;
    ql[ob] = sq * (1.0f / L_POOL);
    kl[ob] = sk * (1.0f / L_POOL);
}

// ---------------- transpose [R,64] -> [64,R], batched ----------------
__global__ void transpose64_kernel(const float* __restrict__ src,
                                   float* __restrict__ dst, int R)
{
    __shared__ float tile[32][33];
    int z = blockIdx.z;
    int r0 = blockIdx.x * 32, c0 = blockIdx.y * 32;
    const float* s = src + (size_t)z * R * 64;
    float* d = dst + (size_t)z * 64 * R;
    tile[threadIdx.y][threadIdx.x] = s[(size_t)(r0 + threadIdx.y) * 64 + c0 + threadIdx.x];
    __syncthreads();
    d[(size_t)(c0 + threadIdx.y) * R + r0 + threadIdx.x] = tile[threadIdx.x][threadIdx.y];
}

// ---------------- row softmax (in-place) ----------------
__global__ __launch_bounds__(256) void softmax_kernel(float* __restrict__ data, int W)
{
    size_t base = (size_t)blockIdx.x * W;
    int t = threadIdx.x;
    __shared__ float sh[256];
    float m = -INFINITY;
    for (int i = t; i < W; i += 256) m = fmaxf(m, data[base + i]);
    sh[t] = m; __syncthreads();
    for (int o = 128; o > 0; o >>= 1) {
        if (t < o) sh[t] = fmaxf(sh[t], sh[t + o]);
        __syncthreads();
    }
    float rowmax = sh[0];
    __syncthreads();
    float s = 0.f;
    for (int i = t; i < W; i += 256) {
        float e = expf(data[base + i] - rowmax);
        data[base + i] = e;
        s += e;
    }
    sh[t] = s; __syncthreads();
    for (int o = 128; o > 0; o >>= 1) {
        if (t < o) sh[t] += sh[t + o];
        __syncthreads();
    }
    float inv = 1.0f / sh[0];
    __syncthreads();
    for (int i = t; i < W; i += 256) data[base + i] *= inv;
}

// ---------------- pinv scale reductions ----------------
__global__ void pinv_scale_zero(unsigned int* scal)
{
    if (threadIdx.x < 2) scal[threadIdx.x] = 0u;
}

__global__ __launch_bounds__(256) void pinv_reduce_kernel(
    const float* __restrict__ a2, unsigned int* scal)
{
    int z = blockIdx.x, t = threadIdx.x;
    const float* m = a2 + (size_t)z * M_LAND * M_LAND;
    float rowsum = 0.f, colsum = 0.f;
    for (int j = 0; j < M_LAND; j++) rowsum += fabsf(m[(size_t)t * M_LAND + j]);
    for (int i = 0; i < M_LAND; i++) colsum += fabsf(m[(size_t)i * M_LAND + t]);
    __shared__ float sh[256];
    sh[t] = rowsum; __syncthreads();
    for (int o = 128; o > 0; o >>= 1) {
        if (t < o) sh[t] = fmaxf(sh[t], sh[t + o]);
        __syncthreads();
    }
    if (t == 0) atomicMax(&scal[0], __float_as_uint(sh[0]));
    __syncthreads();
    sh[t] = colsum; __syncthreads();
    for (int o = 128; o > 0; o >>= 1) {
        if (t < o) sh[t] = fmaxf(sh[t], sh[t + o]);
        __syncthreads();
    }
    if (t == 0) atomicMax(&scal[1], __float_as_uint(sh[0]));
}

__global__ __launch_bounds__(256) void z_init_kernel(
    const float* __restrict__ a2, const unsigned int* __restrict__ scal,
    float* __restrict__ z0)
{
    int z = blockIdx.x, i = blockIdx.y, j = threadIdx.x;
    float inv = 1.0f / (__uint_as_float(scal[0]) * __uint_as_float(scal[1]));
    z0[((size_t)z * M_LAND + j) * M_LAND + i] =
        a2[((size_t)z * M_LAND + i) * M_LAND + j] * inv;
}

// ---------------- depthwise conv residual (adds into outh) ----------------
__global__ __launch_bounds__(256) void conv_res_kernel(
    const float* __restrict__ v, const float* __restrict__ rw,
    float* __restrict__ outh)
{
    __shared__ float sv[96][64];
    __shared__ float w[K_CONV];
    int z = blockIdx.x, h = z & 7;
    int n0 = blockIdx.y * 64;
    int t = threadIdx.x;
    if (t < K_CONV) w[t] = rw[h * K_CONV + t];
    const float* vb = v + (size_t)z * N_SEQ * D_HEAD;
    for (int i = t; i < 96 * 64; i += 256) {
        int r = i >> 6, c = i & 63;
        int n = n0 - PAD_CONV + r;
        sv[r][c] = (n >= 0 && n < N_SEQ) ? vb[(size_t)n * D_HEAD + c] : 0.0f;
    }
    __syncthreads();
    int d = t & 63, r0 = t >> 6;
    for (int rr = r0; rr < 64; rr += 4) {
        float acc = 0.f;
#pragma unroll
        for (int kk = 0; kk < K_CONV; kk++) acc += w[kk] * sv[rr + kk][d];
        outh[(size_t)z * N_SEQ * D_HEAD + (size_t)(n0 + rr) * D_HEAD + d] += acc;
    }
}

// ---------------- merge heads: [b,h,n,dh] -> [b,n,h*dh] ----------------
__global__ __launch_bounds__(256) void merge_heads_kernel(
    const float* __restrict__ outh, float* __restrict__ outt)
{
    size_t idx = (size_t)blockIdx.x * 256 + threadIdx.x;
    int dd = (int)(idx & 63);
    size_t r = idx >> 6;
    int n = (int)(r & 4095);
    int z = (int)(r >> 12);
    int b = z >> 3, h = z & 7;
    outt[((size_t)(b * N_SEQ + n)) * D_MODEL + h * D_HEAD + dd] = outh[idx];
}

// ---------------- host launch ----------------
extern "C" void kernel_launch(void* const* d_in, const int* in_sizes, int n_in,
                              void* d_out, int out_size)
{
    (void)in_sizes; (void)n_in; (void)out_size;
    const float* x     = (const float*)d_in[0];
    const float* gamma = (const float*)d_in[1];
    const float* beta  = (const float*)d_in[2];
    const float* w_qkv = (const float*)d_in[3];
    const float* w_out = (const float*)d_in[4];
    const float* b_out = (const float*)d_in[5];
    const float* res_w = (const float*)d_in[6];
    float* out = (float*)d_out;

    float *xn, *q, *k, *v, *ql, *kl, *kT, *klT, *a1, *a3, *a2;
    float *z0, *z1, *xz, *w2, *w3, *a3v, *t1, *outh, *outt;
    unsigned int* scal;
    cudaGetSymbolAddress((void**)&xn,  g_xn);
    cudaGetSymbolAddress((void**)&q,   g_q);
    cudaGetSymbolAddress((void**)&k,   g_k);
    cudaGetSymbolAddress((void**)&v,   g_v);
    cudaGetSymbolAddress((void**)&ql,  g_ql);
    cudaGetSymbolAddress((void**)&kl,  g_kl);
    cudaGetSymbolAddress((void**)&kT,  g_kT);
    cudaGetSymbolAddress((void**)&klT, g_klT);
    cudaGetSymbolAddress((void**)&a1,  g_a1);
    cudaGetSymbolAddress((void**)&a3,  g_a3);
    cudaGetSymbolAddress((void**)&a2,  g_a2);
    cudaGetSymbolAddress((void**)&z0,  g_z0);
    cudaGetSymbolAddress((void**)&z1,  g_z1);
    cudaGetSymbolAddress((void**)&xz,  g_xz);
    cudaGetSymbolAddress((void**)&w2,  g_w2);
    cudaGetSymbolAddress((void**)&w3,  g_w3);
    cudaGetSymbolAddress((void**)&a3v, g_a3v);
    cudaGetSymbolAddress((void**)&t1,  g_t1);
    cudaGetSymbolAddress((void**)&outh, g_outh);
    cudaGetSymbolAddress((void**)&outt, g_outt);
    cudaGetSymbolAddress((void**)&scal, g_scal);

    const size_t SZ2 = (size_t)M_LAND * M_LAND;

    // 1. LayerNorm
    ln_kernel<<<N_ROWS, 256>>>(x, gamma, beta, xn);

    // 2. QKV GEMM with scatter-to-heads epilogue (q scaled)
    {
        EpiQKV e{q, k, v};
        gemm_tf32<128, 128, 64, 32, EpiQKV><<<dim3(1536 / 128, N_ROWS / 128, 1), 256>>>(
            xn, 0, D_MODEL, w_qkv, 0, 3 * D_MODEL, D_MODEL, e);
    }

    // 3. landmark pooling
    landmark_kernel<<<dim3(N_BH, M_LAND), 64>>>(q, k, ql, kl);

    // 4. transposes so sims are NN GEMMs
    transpose64_kernel<<<dim3(N_SEQ / 32, 2, N_BH), dim3(32, 32)>>>(k, kT, N_SEQ);
    transpose64_kernel<<<dim3(M_LAND / 32, 2, N_BH), dim3(32, 32)>>>(kl, klT, M_LAND);

    // 5. similarity GEMMs
    {   // sim1 = q @ k_l^T   [bh, 4096, 256]
        EpiStd e{a1, (size_t)N_SEQ * M_LAND, M_LAND, 1.f, 0.f, nullptr, 0, nullptr};
        gemm_tf32<128, 128, 64, 32, EpiStd><<<dim3(M_LAND / 128, N_SEQ / 128, N_BH), 256>>>(
            q, (size_t)N_SEQ * D_HEAD, D_HEAD, klT, (size_t)D_HEAD * M_LAND, M_LAND, D_HEAD, e);
    }
    {   // sim2 = q_l @ k_l^T [bh, 256, 256]
        EpiStd e{a2, SZ2, M_LAND, 1.f, 0.f, nullptr, 0, nullptr};
        gemm_tf32<128, 128, 64, 32, EpiStd><<<dim3(2, 2, N_BH), 256>>>(
            ql, (size_t)M_LAND * D_HEAD, D_HEAD, klT, (size_t)D_HEAD * M_LAND, M_LAND, D_HEAD, e);
    }
    {   // sim3 = q_l @ k^T   [bh, 256, 4096]
        EpiStd e{a3, (size_t)M_LAND * N_SEQ, N_SEQ, 1.f, 0.f, nullptr, 0, nullptr};
        gemm_tf32<128, 128, 64, 32, EpiStd><<<dim3(N_SEQ / 128, 2, N_BH), 256>>>(
            ql, (size_t)M_LAND * D_HEAD, D_HEAD, kT, (size_t)D_HEAD * N_SEQ, N_SEQ, D_HEAD, e);
    }

    // 6. softmaxes (in place)
    softmax_kernel<<<N_BH * N_SEQ, 256>>>(a1, M_LAND);
    softmax_kernel<<<N_BH * M_LAND, 256>>>(a2, M_LAND);
    softmax_kernel<<<N_BH * M_LAND, 256>>>(a3, N_SEQ);

    // 7. pinv init: z0 = a2^T / (max(rowsums) * max(colsums))  (global maxes)
    pinv_scale_zero<<<1, 32>>>(scal);
    pinv_reduce_kernel<<<N_BH, 256>>>(a2, scal);
    z_init_kernel<<<dim3(N_BH, M_LAND), 256>>>(a2, scal, z0);

    // 8. Newton-Schulz iterations (pure GEMMs with fused epilogues)
    float* zc = z0;
    float* zn = z1;
    for (int it = 0; it < PINV_ITERS; it++) {
        {   // xz = a2 @ z
            EpiStd e{xz, SZ2, M_LAND, 1.f, 0.f, nullptr, 0, nullptr};
            gemm_tf32<128, 128, 64, 32, EpiStd><<<dim3(2, 2, N_BH), 256>>>(
                a2, SZ2, M_LAND, zc, SZ2, M_LAND, M_LAND, e);
        }
        {   // w2 = xz @ (7I - xz) = 7*xz - xz@xz
            EpiStd e{w2, SZ2, M_LAND, -1.f, 7.f, xz, SZ2, nullptr};
            gemm_tf32<128, 128, 64, 32, EpiStd><<<dim3(2, 2, N_BH), 256>>>(
                xz, SZ2, M_LAND, xz, SZ2, M_LAND, M_LAND, e);
        }
        {   // w3 = xz @ (15I - w2) = 15*xz - xz@w2
            EpiStd e{w3, SZ2, M_LAND, -1.f, 15.f, xz, SZ2, nullptr};
            gemm_tf32<128, 128, 64, 32, EpiStd><<<dim3(2, 2, N_BH), 256>>>(
                xz, SZ2, M_LAND, w2, SZ2, M_LAND, M_LAND, e);
        }
        {   // z' = 0.25 * z @ (13I - w3) = 3.25*z - 0.25*z@w3
            EpiStd e{zn, SZ2, M_LAND, -0.25f, 3.25f, zc, SZ2, nullptr};
            gemm_tf32<128, 128, 64, 32, EpiStd><<<dim3(2, 2, N_BH), 256>>>(
                zc, SZ2, M_LAND, w3, SZ2, M_LAND, M_LAND, e);
        }
        float* tswap = zc; zc = zn; zn = tswap;
    }

    // 9. a3v = a3 @ v   [bh, 256, 64]   (64x64 tiles -> 128 blocks)
    {
        EpiStd e{a3v, (size_t)M_LAND * D_HEAD, D_HEAD, 1.f, 0.f, nullptr, 0, nullptr};
        gemm_tf32<64, 64, 32, 16, EpiStd><<<dim3(1, M_LAND / 64, N_BH), 256>>>(
            a3, (size_t)M_LAND * N_SEQ, N_SEQ, v, (size_t)N_SEQ * D_HEAD, D_HEAD, N_SEQ, e);
    }
    // 10. t1 = a1 @ z_final  [bh, 4096, 256]
    {
        EpiStd e{t1, (size_t)N_SEQ * M_LAND, M_LAND, 1.f, 0.f, nullptr, 0, nullptr};
        gemm_tf32<128, 128, 64, 32, EpiStd><<<dim3(2, N_SEQ / 128, N_BH), 256>>>(
            a1, (size_t)N_SEQ * M_LAND, M_LAND, zc, SZ2, M_LAND, M_LAND, e);
    }
    // 11. outh = t1 @ a3v  [bh, 4096, 64]   (64x64 tiles -> 2048 blocks)
    {
        EpiStd e{outh, (size_t)N_SEQ * D_HEAD, D_HEAD, 1.f, 0.f, nullptr, 0, nullptr};
        gemm_tf32<64, 64, 32, 16, EpiStd><<<dim3(1, N_SEQ / 64, N_BH), 256>>>(
            t1, (size_t)N_SEQ * M_LAND, M_LAND, a3v, (size_t)M_LAND * D_HEAD, D_HEAD, M_LAND, e);
    }

    // 12. depthwise conv residual (adds into outh)
    conv_res_kernel<<<dim3(N_BH, N_SEQ / 64), 256>>>(v, res_w, outh);

    // 13. merge heads
    merge_heads_kernel<<<((size_t)N_ROWS * D_MODEL) / 256, 256>>>(outh, outt);

    // 14. final GEMM: out = x + outt @ w_out + b_out
    {
        EpiStd e{out, 0, D_MODEL, 1.f, 1.f, x, 0, b_out};
        gemm_tf32<128, 128, 64, 32, EpiStd><<<dim3(D_MODEL / 128, N_ROWS / 128, 1), 256>>>(
            outt, 0, D_MODEL, w_out, 0, D_MODEL, D_MODEL, e);
    }
}

// round 3
// speedup vs baseline: 3.5750x; 1.5011x over previous
#include <cuda_runtime.h>
#include <math.h>
#include <stdint.h>

// ---------------- problem constants ----------------
#define N_BATCH 4
#define N_SEQ   4096
#define D_MODEL 512
#define N_HEADS 8
#define D_HEAD  64
#define M_LAND  256
#define L_POOL  16
#define N_BH    32
#define N_ROWS  16384
#define PINV_ITERS 6
#define K_CONV  33
#define PAD_CONV 16
#define LN_EPS  1e-5f
#define Q_SCALE 0.125f

// ---------------- device scratch ----------------
__device__ float g_xn  [(size_t)N_ROWS * D_MODEL];
__device__ float g_q   [(size_t)N_BH * N_SEQ * D_HEAD];
__device__ float g_k   [(size_t)N_BH * N_SEQ * D_HEAD];
__device__ float g_v   [(size_t)N_BH * N_SEQ * D_HEAD];
__device__ float g_ql  [(size_t)N_BH * M_LAND * D_HEAD];
__device__ float g_kl  [(size_t)N_BH * M_LAND * D_HEAD];
__device__ float g_a2  [(size_t)N_BH * M_LAND * M_LAND];
__device__ float g_z0  [(size_t)N_BH * M_LAND * M_LAND];
__device__ float g_z1  [(size_t)N_BH * M_LAND * M_LAND];
__device__ float g_xz  [(size_t)N_BH * M_LAND * M_LAND];
__device__ float g_w2  [(size_t)N_BH * M_LAND * M_LAND];
__device__ float g_w3  [(size_t)N_BH * M_LAND * M_LAND];
__device__ float g_a3v [(size_t)N_BH * M_LAND * D_HEAD];
__device__ float g_zv  [(size_t)N_BH * M_LAND * D_HEAD];
__device__ float g_outt[(size_t)N_ROWS * D_MODEL];
__device__ unsigned int g_scal[2];

// ---------------- tf32 helpers ----------------
__device__ __forceinline__ float tf32r(float x) {
    uint32_t u;
    asm("cvt.rna.tf32.f32 %0, %1;" : "=r"(u) : "f"(x));
    return __uint_as_float(u);
}

__device__ __forceinline__ void mma_tf32(float* d, const uint32_t* a, const uint32_t* b) {
    asm volatile(
        "mma.sync.aligned.m16n8k8.row.col.f32.tf32.tf32.f32 "
        "{%0,%1,%2,%3}, {%4,%5,%6,%7}, {%8,%9}, {%0,%1,%2,%3};\n"
        : "+f"(d[0]), "+f"(d[1]), "+f"(d[2]), "+f"(d[3])
        : "r"(a[0]), "r"(a[1]), "r"(a[2]), "r"(a[3]), "r"(b[0]), "r"(b[1]));
}

// ---------------- LayerNorm ----------------
__global__ __launch_bounds__(256) void ln_kernel(
    const float* __restrict__ x, const float* __restrict__ gamma,
    const float* __restrict__ beta, float* __restrict__ xn)
{
    int row = blockIdx.x;
    int t = threadIdx.x;
    const float* xr = x + (size_t)row * D_MODEL;
    float v0 = xr[t], v1 = xr[t + 256];
    __shared__ float ssum[256], ssq[256];
    ssum[t] = v0 + v1;
    ssq[t]  = v0 * v0 + v1 * v1;
    __syncthreads();
    for (int o = 128; o > 0; o >>= 1) {
        if (t < o) { ssum[t] += ssum[t + o]; ssq[t] += ssq[t + o]; }
        __syncthreads();
    }
    float mean = ssum[0] * (1.0f / D_MODEL);
    float var  = ssq[0] * (1.0f / D_MODEL) - mean * mean;
    float rstd = rsqrtf(var + LN_EPS);
    float* o = xn + (size_t)row * D_MODEL;
    o[t]       = (v0 - mean) * rstd * gamma[t]       + beta[t];
    o[t + 256] = (v1 - mean) * rstd * gamma[t + 256] + beta[t + 256];
}

// ---------------- epilogue functors ----------------
struct EpiStd {
    float* C; size_t cStride; int ldc;
    float c1, c2;
    const float* Add; size_t addStride;
    const float* bias;
    __device__ __forceinline__ void operator()(int z, int row, int col, float acc) const {
        float val = c1 * acc;
        if (Add)  val += c2 * Add[(size_t)z * addStride + (size_t)row * ldc + col];
        if (bias) val += bias[col];
        C[(size_t)z * cStride + (size_t)row * ldc + col] = val;
    }
};

struct EpiQKV {
    float* q; float* k; float* v;
    __device__ __forceinline__ void operator()(int z, int row, int col, float acc) const {
        (void)z;
        int which = col >> 9;
        int d = col & 511;
        int h = d >> 6, dd = d & 63;
        int b = row >> 12, n = row & 4095;
        size_t o = (((size_t)(b * N_HEADS + h)) * N_SEQ + n) * D_HEAD + dd;
        if (which == 0)      q[o] = acc * Q_SCALE;
        else if (which == 1) k[o] = acc;
        else                 v[o] = acc;
    }
};

// ---------------- tf32 tensor-core GEMM (NN, row-major) ----------------
template<int BM, int BN, int WM, int WN, class Epi>
__global__ __launch_bounds__(256) void gemm_tf32(
    const float* __restrict__ A, size_t aStride, int lda,
    const float* __restrict__ B, size_t bStride, int ldb,
    int K, Epi epi)
{
    constexpr int WARPS_M = BM / WM;
    constexpr int WARPS_N = BN / WN;
    static_assert(WARPS_M * WARPS_N == 8, "need 8 warps");
    constexpr int MT  = WM / 16;
    constexpr int NTL = WN / 8;
    constexpr int AP  = 36;
    constexpr int BNP = BN + 8;

    __shared__ float As[BM][AP];
    __shared__ float Bs[32][BNP];

    const int tid  = threadIdx.x;
    const int lane = tid & 31;
    const int warp = tid >> 5;
    const int wm = warp % WARPS_M;
    const int wn = warp / WARPS_M;
    const int g  = lane >> 2;
    const int t4 = lane & 3;
    const int z  = blockIdx.z;
    const int rowBase = blockIdx.y * BM;
    const int colBase = blockIdx.x * BN;
    const float* Ab = A + (size_t)z * aStride + (size_t)rowBase * lda;
    const float* Bb = B + (size_t)z * bStride + colBase;

    float acc[MT][NTL][4];
#pragma unroll
    for (int i = 0; i < MT; i++)
#pragma unroll
        for (int j = 0; j < NTL; j++) {
            acc[i][j][0] = 0.f; acc[i][j][1] = 0.f;
            acc[i][j][2] = 0.f; acc[i][j][3] = 0.f;
        }

    for (int k0 = 0; k0 < K; k0 += 32) {
#pragma unroll
        for (int i = tid; i < BM * 8; i += 256) {
            int r = i >> 3, c4 = (i & 7) << 2;
            float4 va = *(const float4*)&Ab[(size_t)r * lda + k0 + c4];
            float4 t;
            t.x = tf32r(va.x); t.y = tf32r(va.y);
            t.z = tf32r(va.z); t.w = tf32r(va.w);
            *(float4*)&As[r][c4] = t;
        }
#pragma unroll
        for (int i = tid; i < BN * 8; i += 256) {
            int r = i / (BN / 4), c = (i % (BN / 4)) << 2;
            float4 vb = *(const float4*)&Bb[(size_t)(k0 + r) * ldb + c];
            float4 t;
            t.x = tf32r(vb.x); t.y = tf32r(vb.y);
            t.z = tf32r(vb.z); t.w = tf32r(vb.w);
            *(float4*)&Bs[r][c] = t;
        }
        __syncthreads();

#pragma unroll
        for (int kk = 0; kk < 32; kk += 8) {
            uint32_t af[MT][4], bf[NTL][2];
#pragma unroll
            for (int mt = 0; mt < MT; mt++) {
                int r = wm * WM + mt * 16 + g;
                af[mt][0] = __float_as_uint(As[r][kk + t4]);
                af[mt][1] = __float_as_uint(As[r + 8][kk + t4]);
                af[mt][2] = __float_as_uint(As[r][kk + t4 + 4]);
                af[mt][3] = __float_as_uint(As[r + 8][kk + t4 + 4]);
            }
#pragma unroll
            for (int nt = 0; nt < NTL; nt++) {
                int c = wn * WN + nt * 8 + g;
                bf[nt][0] = __float_as_uint(Bs[kk + t4][c]);
                bf[nt][1] = __float_as_uint(Bs[kk + t4 + 4][c]);
            }
#pragma unroll
            for (int mt = 0; mt < MT; mt++)
#pragma unroll
                for (int nt = 0; nt < NTL; nt++)
                    mma_tf32(acc[mt][nt], af[mt], bf[nt]);
        }
        __syncthreads();
    }

#pragma unroll
    for (int mt = 0; mt < MT; mt++) {
        int row0 = rowBase + wm * WM + mt * 16 + g;
#pragma unroll
        for (int nt = 0; nt < NTL; nt++) {
            int col = colBase + wn * WN + nt * 8 + t4 * 2;
            epi(z, row0,     col,     acc[mt][nt][0]);
            epi(z, row0,     col + 1, acc[mt][nt][1]);
            epi(z, row0 + 8, col,     acc[mt][nt][2]);
            epi(z, row0 + 8, col + 1, acc[mt][nt][3]);
        }
    }
}

// ---------------- fused flash attention (tf32 mma) ----------------
// out = softmax(Q @ K^T) @ V, per batched head z.
// BM=64 q rows/block, BN=128 key chunk, 4 warps (WM=16 each).
// OUT_MODE 0: O[z*nq + row][64] contiguous.  OUT_MODE 1: O = outt[b,n,512] at col h*64.
template<int BM, int BN, int NWARP, int OUT_MODE>
__global__ void __launch_bounds__(NWARP * 32, 2) flash_kernel(
    const float* __restrict__ Q, const float* __restrict__ K,
    const float* __restrict__ V, float* __restrict__ O,
    int nk, int nq)
{
    constexpr int NT = NWARP * 32;
    constexpr int AP = 76;                 // pad for [rows][64] operand tiles
    constexpr int PP = BN + 4;             // pad for P tile [BM][BN]
    constexpr int NTS = BN / 8;            // S col fragments (16)
    constexpr int NTO = D_HEAD / 8;        // O col fragments (8)
    constexpr int KP_SZ = (BN * AP > BM * PP) ? BN * AP : BM * PP;

    extern __shared__ float sm[];
    float* Qs  = sm;                       // [BM][AP]
    float* KPs = sm + BM * AP;             // K chunk [BN][AP], reused as P [BM][PP]
    float* Vs  = KPs + KP_SZ;              // [BN][AP]

    const int tid  = threadIdx.x;
    const int lane = tid & 31;
    const int warp = tid >> 5;
    const int g  = lane >> 2;
    const int t4 = lane & 3;
    const int z  = blockIdx.y;
    const int r0 = warp * 16 + g;          // thread's row pair: r0, r0+8

    const float* Qb = Q + ((size_t)z * nq + (size_t)blockIdx.x * BM) * D_HEAD;
    const float* Kb = K + (size_t)z * nk * D_HEAD;
    const float* Vb = V + (size_t)z * nk * D_HEAD;

    // stage Q (tf32)
#pragma unroll
    for (int i = tid; i < BM * 16; i += NT) {
        int r = i >> 4, c4 = (i & 15) << 2;
        float4 va = *(const float4*)(Qb + (size_t)r * D_HEAD + c4);
        float4 t;
        t.x = tf32r(va.x); t.y = tf32r(va.y);
        t.z = tf32r(va.z); t.w = tf32r(va.w);
        *(float4*)&Qs[r * AP + c4] = t;
    }

    float m0 = -INFINITY, m1 = -INFINITY, l0 = 0.f, l1 = 0.f;
    float o[NTO][4];
#pragma unroll
    for (int j = 0; j < NTO; j++) { o[j][0] = o[j][1] = o[j][2] = o[j][3] = 0.f; }

    for (int chunk = 0; chunk < nk; chunk += BN) {
        // stage K, V chunks (tf32)
#pragma unroll
        for (int i = tid; i < BN * 16; i += NT) {
            int r = i >> 4, c4 = (i & 15) << 2;
            float4 vk = *(const float4*)(Kb + (size_t)(chunk + r) * D_HEAD + c4);
            float4 vv = *(const float4*)(Vb + (size_t)(chunk + r) * D_HEAD + c4);
            float4 tk, tv;
            tk.x = tf32r(vk.x); tk.y = tf32r(vk.y); tk.z = tf32r(vk.z); tk.w = tf32r(vk.w);
            tv.x = tf32r(vv.x); tv.y = tf32r(vv.y); tv.z = tf32r(vv.z); tv.w = tf32r(vv.w);
            *(float4*)&KPs[r * AP + c4] = tk;
            *(float4*)&Vs[r * AP + c4]  = tv;
        }
        __syncthreads();

        // S = Q @ K^T   [BM x BN]
        float s[NTS][4];
#pragma unroll
        for (int nt = 0; nt < NTS; nt++) { s[nt][0] = s[nt][1] = s[nt][2] = s[nt][3] = 0.f; }
#pragma unroll
        for (int kk = 0; kk < D_HEAD; kk += 8) {
            uint32_t af[4];
            af[0] = __float_as_uint(Qs[r0 * AP + kk + t4]);
            af[1] = __float_as_uint(Qs[(r0 + 8) * AP + kk + t4]);
            af[2] = __float_as_uint(Qs[r0 * AP + kk + t4 + 4]);
            af[3] = __float_as_uint(Qs[(r0 + 8) * AP + kk + t4 + 4]);
#pragma unroll
            for (int nt = 0; nt < NTS; nt++) {
                uint32_t bf[2];
                int c = nt * 8 + g;
                bf[0] = __float_as_uint(KPs[c * AP + kk + t4]);
                bf[1] = __float_as_uint(KPs[c * AP + kk + t4 + 4]);
                mma_tf32(s[nt], af, bf);
            }
        }

        // online softmax (rows r0, r0+8)
        float nm0 = m0, nm1 = m1;
#pragma unroll
        for (int nt = 0; nt < NTS; nt++) {
            nm0 = fmaxf(nm0, fmaxf(s[nt][0], s[nt][1]));
            nm1 = fmaxf(nm1, fmaxf(s[nt][2], s[nt][3]));
        }
        nm0 = fmaxf(nm0, __shfl_xor_sync(0xffffffffu, nm0, 1));
        nm0 = fmaxf(nm0, __shfl_xor_sync(0xffffffffu, nm0, 2));
        nm1 = fmaxf(nm1, __shfl_xor_sync(0xffffffffu, nm1, 1));
        nm1 = fmaxf(nm1, __shfl_xor_sync(0xffffffffu, nm1, 2));
        float alpha0 = expf(m0 - nm0);
        float alpha1 = expf(m1 - nm1);
        float rs0 = 0.f, rs1 = 0.f;
#pragma unroll
        for (int nt = 0; nt < NTS; nt++) {
            s[nt][0] = expf(s[nt][0] - nm0);
            s[nt][1] = expf(s[nt][1] - nm0);
            s[nt][2] = expf(s[nt][2] - nm1);
            s[nt][3] = expf(s[nt][3] - nm1);
            rs0 += s[nt][0] + s[nt][1];
            rs1 += s[nt][2] + s[nt][3];
        }
        rs0 += __shfl_xor_sync(0xffffffffu, rs0, 1);
        rs0 += __shfl_xor_sync(0xffffffffu, rs0, 2);
        rs1 += __shfl_xor_sync(0xffffffffu, rs1, 1);
        rs1 += __shfl_xor_sync(0xffffffffu, rs1, 2);
        l0 = l0 * alpha0 + rs0;
        l1 = l1 * alpha1 + rs1;
        m0 = nm0; m1 = nm1;

        __syncthreads();   // all warps done reading K before P overwrites it
        // store P (tf32) into KPs as [BM][PP]
#pragma unroll
        for (int nt = 0; nt < NTS; nt++) {
            int c = nt * 8 + 2 * t4;
            float2 p01 = make_float2(tf32r(s[nt][0]), tf32r(s[nt][1]));
            float2 p23 = make_float2(tf32r(s[nt][2]), tf32r(s[nt][3]));
            *(float2*)&KPs[r0 * PP + c]       = p01;
            *(float2*)&KPs[(r0 + 8) * PP + c] = p23;
        }
        __syncthreads();

        // rescale O
#pragma unroll
        for (int j = 0; j < NTO; j++) {
            o[j][0] *= alpha0; o[j][1] *= alpha0;
            o[j][2] *= alpha1; o[j][3] *= alpha1;
        }

        // O += P @ V   [BM x 64], k-dim = BN
#pragma unroll
        for (int kk = 0; kk < BN; kk += 8) {
            uint32_t af[4];
            af[0] = __float_as_uint(KPs[r0 * PP + kk + t4]);
            af[1] = __float_as_uint(KPs[(r0 + 8) * PP + kk + t4]);
            af[2] = __float_as_uint(KPs[r0 * PP + kk + t4 + 4]);
            af[3] = __float_as_uint(KPs[(r0 + 8) * PP + kk + t4 + 4]);
#pragma unroll
            for (int j = 0; j < NTO; j++) {
                uint32_t bf[2];
                int c = j * 8 + g;
                bf[0] = __float_as_uint(Vs[(kk + t4) * AP + c]);
                bf[1] = __float_as_uint(Vs[(kk + t4 + 4) * AP + c]);
                mma_tf32(o[j], af, bf);
            }
        }
        __syncthreads();   // before next chunk overwrites KPs/Vs
    }

    // epilogue: normalize and store
    float inv0 = 1.0f / l0;
    float inv1 = 1.0f / l1;
    int row = blockIdx.x * BM + r0;
    if (OUT_MODE == 0) {
        float* ob = O + ((size_t)z * nq + row) * D_HEAD;
#pragma unroll
        for (int j = 0; j < NTO; j++) {
            int c = j * 8 + 2 * t4;
            ob[c]     = o[j][0] * inv0;
            ob[c + 1] = o[j][1] * inv0;
            ob[8 * D_HEAD + c]     = o[j][2] * inv1;
            ob[8 * D_HEAD + c + 1] = o[j][3] * inv1;
        }
    } else {
        int b = z >> 3, h = z & 7;
        float* ob = O + ((size_t)(b * N_SEQ + row)) * D_MODEL + h * D_HEAD;
#pragma unroll
        for (int j = 0; j < NTO; j++) {
            int c = j * 8 + 2 * t4;
            ob[c]     = o[j][0] * inv0;
            ob[c + 1] = o[j][1] * inv0;
            ob[8 * D_MODEL + c]     = o[j][2] * inv1;
            ob[8 * D_MODEL + c + 1] = o[j][3] * inv1;
        }
    }
}

// ---------------- landmark pooling ----------------
__global__ __launch_bounds__(64) void landmark_kernel(
    const float* __restrict__ q, const float* __restrict__ k,
    float* __restrict__ ql, float* __restrict__ kl)
{
    int z = blockIdx.x, m = blockIdx.y, d = threadIdx.x;
    size_t inb = ((size_t)z * N_SEQ + (size_t)m * L_POOL) * D_HEAD + d;
    float sq = 0.f, sk = 0.f;
#pragma unroll
    for (int l = 0; l < L_POOL; l++) {
        sq += q[inb + (size_t)l * D_HEAD];
        sk += k[inb + (size_t)l * D_HEAD];
    }
    size_t ob = ((size_t)z * M_LAND + m) * D_HEAD + d;
    ql[ob] = sq * (1.0f / L_POOL);
    kl[ob] = sk * (1.0f / L_POOL);
}

// ---------------- row softmax (in-place, W=256) ----------------
__global__ __launch_bounds__(256) void softmax_kernel(float* __restrict__ data, int W)
{
    size_t base = (size_t)blockIdx.x * W;
    int t = threadIdx.x;
    __shared__ float sh[256];
    float m = -INFINITY;
    for (int i = t; i < W; i += 256) m = fmaxf(m, data[base + i]);
    sh[t] = m; __syncthreads();
    for (int o = 128; o > 0; o >>= 1) {
        if (t < o) sh[t] = fmaxf(sh[t], sh[t + o]);
        __syncthreads();
    }
    float rowmax = sh[0];
    __syncthreads();
    float s = 0.f;
    for (int i = t; i < W; i += 256) {
        float e = expf(data[base + i] - rowmax);
        data[base + i] = e;
        s += e;
    }
    sh[t] = s; __syncthreads();
    for (int o = 128; o > 0; o >>= 1) {
        if (t < o) sh[t] += sh[t + o];
        __syncthreads();
    }
    float inv = 1.0f / sh[0];
    __syncthreads();
    for (int i = t; i < W; i += 256) data[base + i] *= inv;
}

// ---------------- pinv scale reductions ----------------
__global__ void pinv_scale_zero(unsigned int* scal)
{
    if (threadIdx.x < 2) scal[threadIdx.x] = 0u;
}

__global__ __launch_bounds__(256) void pinv_reduce_kernel(
    const float* __restrict__ a2, unsigned int* scal)
{
    int z = blockIdx.x, t = threadIdx.x;
    const float* m = a2 + (size_t)z * M_LAND * M_LAND;
    float rowsum = 0.f, colsum = 0.f;
    for (int j = 0; j < M_LAND; j++) rowsum += fabsf(m[(size_t)t * M_LAND + j]);
    for (int i = 0; i < M_LAND; i++) colsum += fabsf(m[(size_t)i * M_LAND + t]);
    __shared__ float sh[256];
    sh[t] = rowsum; __syncthreads();
    for (int o = 128; o > 0; o >>= 1) {
        if (t < o) sh[t] = fmaxf(sh[t], sh[t + o]);
        __syncthreads();
    }
    if (t == 0) atomicMax(&scal[0], __float_as_uint(sh[0]));
    __syncthreads();
    sh[t] = colsum; __syncthreads();
    for (int o = 128; o > 0; o >>= 1) {
        if (t < o) sh[t] = fmaxf(sh[t], sh[t + o]);
        __syncthreads();
    }
    if (t == 0) atomicMax(&scal[1], __float_as_uint(sh[0]));
}

__global__ __launch_bounds__(256) void z_init_kernel(
    const float* __restrict__ a2, const unsigned int* __restrict__ scal,
    float* __restrict__ z0)
{
    int z = blockIdx.x, i = blockIdx.y, j = threadIdx.x;
    float inv = 1.0f / (__uint_as_float(scal[0]) * __uint_as_float(scal[1]));
    z0[((size_t)z * M_LAND + j) * M_LAND + i] =
        a2[((size_t)z * M_LAND + i) * M_LAND + j] * inv;
}

// ---------------- depthwise conv residual (adds into outt layout) ----------------
__global__ __launch_bounds__(256) void conv_res_kernel(
    const float* __restrict__ v, const float* __restrict__ rw,
    float* __restrict__ outt)
{
    __shared__ float sv[96][64];
    __shared__ float w[K_CONV];
    int z = blockIdx.x, h = z & 7, bb = z >> 3;
    int n0 = blockIdx.y * 64;
    int t = threadIdx.x;
    if (t < K_CONV) w[t] = rw[h * K_CONV + t];
    const float* vb = v + (size_t)z * N_SEQ * D_HEAD;
    for (int i = t; i < 96 * 64; i += 256) {
        int r = i >> 6, c = i & 63;
        int n = n0 - PAD_CONV + r;
        sv[r][c] = (n >= 0 && n < N_SEQ) ? vb[(size_t)n * D_HEAD + c] : 0.0f;
    }
    __syncthreads();
    int d = t & 63, r0 = t >> 6;
    for (int rr = r0; rr < 64; rr += 4) {
        float acc = 0.f;
#pragma unroll
        for (int kk = 0; kk < K_CONV; kk++) acc += w[kk] * sv[rr + kk][d];
        outt[((size_t)(bb * N_SEQ + n0 + rr)) * D_MODEL + h * D_HEAD + d] += acc;
    }
}

// ---------------- host launch ----------------
extern "C" void kernel_launch(void* const* d_in, const int* in_sizes, int n_in,
                              void* d_out, int out_size)
{
    (void)in_sizes; (void)n_in; (void)out_size;
    const float* x     = (const float*)d_in[0];
    const float* gamma = (const float*)d_in[1];
    const float* beta  = (const float*)d_in[2];
    const float* w_qkv = (const float*)d_in[3];
    const float* w_out = (const float*)d_in[4];
    const float* b_out = (const float*)d_in[5];
    const float* res_w = (const float*)d_in[6];
    float* out = (float*)d_out;

    float *xn, *q, *k, *v, *ql, *kl, *a2;
    float *z0, *z1, *xz, *w2, *w3, *a3v, *zv, *outt;
    unsigned int* scal;
    cudaGetSymbolAddress((void**)&xn,  g_xn);
    cudaGetSymbolAddress((void**)&q,   g_q);
    cudaGetSymbolAddress((void**)&k,   g_k);
    cudaGetSymbolAddress((void**)&v,   g_v);
    cudaGetSymbolAddress((void**)&ql,  g_ql);
    cudaGetSymbolAddress((void**)&kl,  g_kl);
    cudaGetSymbolAddress((void**)&a2,  g_a2);
    cudaGetSymbolAddress((void**)&z0,  g_z0);
    cudaGetSymbolAddress((void**)&z1,  g_z1);
    cudaGetSymbolAddress((void**)&xz,  g_xz);
    cudaGetSymbolAddress((void**)&w2,  g_w2);
    cudaGetSymbolAddress((void**)&w3,  g_w3);
    cudaGetSymbolAddress((void**)&a3v, g_a3v);
    cudaGetSymbolAddress((void**)&zv,  g_zv);
    cudaGetSymbolAddress((void**)&outt, g_outt);
    cudaGetSymbolAddress((void**)&scal, g_scal);

    const size_t SZ2 = (size_t)M_LAND * M_LAND;

    // flash smem size: Q[64][76] + max(K[128][76], P[64][132]) + V[128][76]
    constexpr int FLASH_SMEM = (64 * 76 + 128 * 76 + 128 * 76) * 4;  // 97280 B
    static bool attr_done = false;
    if (!attr_done) {
        cudaFuncSetAttribute(flash_kernel<64, 128, 4, 0>,
                             cudaFuncAttributeMaxDynamicSharedMemorySize, FLASH_SMEM);
        cudaFuncSetAttribute(flash_kernel<64, 128, 4, 1>,
                             cudaFuncAttributeMaxDynamicSharedMemorySize, FLASH_SMEM);
        attr_done = true;
    }

    // 1. LayerNorm
    ln_kernel<<<N_ROWS, 256>>>(x, gamma, beta, xn);

    // 2. QKV GEMM with scatter-to-heads epilogue (q scaled)
    {
        EpiQKV e{q, k, v};
        gemm_tf32<128, 128, 64, 32, EpiQKV><<<dim3(1536 / 128, N_ROWS / 128, 1), 256>>>(
            xn, 0, D_MODEL, w_qkv, 0, 3 * D_MODEL, D_MODEL, e);
    }

    // 3. landmark pooling
    landmark_kernel<<<dim3(N_BH, M_LAND), 64>>>(q, k, ql, kl);

    // 4. sim2 = q_l @ k_l^T (via flash-style? no — plain GEMM, B=kl as col layout)
    //    Use gemm with klT? kl is [M,64] row-major; we need klT [64,M] for NN gemm.
    //    Instead: a2 via flash S-only is overkill — reuse mma gemm with kl staged
    //    as B by treating it through a tiny dedicated path: transpose-free via
    //    flash kernel would need softmax... keep NN gemm on klT computed inline:
    //    cheap: compute a2 with flash-style S kernel is more code; instead do
    //    gemm_tf32 with A=ql, B=kl^T by staging: we emulate by using kl with
    //    ldb trick is not possible. Use small transpose into xz buffer (scratch).
    {
        // transpose kl [M,64] -> klT in xz scratch [64,M] per z (runs before pinv uses xz)
        // simple kernel reusing conv-free path:
        // (inline lambda-style kernel below)
    }
    // small transpose kernel for kl
    {
        struct { } _;
        (void)_;
    }
    // use transpose64-style kernel:
    extern __global__ void transpose64_kernel(const float*, float*, int);
    transpose64_kernel<<<dim3(M_LAND / 32, 2, N_BH), dim3(32, 32)>>>(kl, xz, M_LAND);
    {   // a2 = ql @ klT  [bh, 256, 256]
        EpiStd e{a2, SZ2, M_LAND, 1.f, 0.f, nullptr, 0, nullptr};
        gemm_tf32<128, 128, 64, 32, EpiStd><<<dim3(2, 2, N_BH), 256>>>(
            ql, (size_t)M_LAND * D_HEAD, D_HEAD, xz, (size_t)D_HEAD * M_LAND, M_LAND, D_HEAD, e);
    }
    softmax_kernel<<<N_BH * M_LAND, 256>>>(a2, M_LAND);

    // 5. pinv init
    pinv_scale_zero<<<1, 32>>>(scal);
    pinv_reduce_kernel<<<N_BH, 256>>>(a2, scal);
    z_init_kernel<<<dim3(N_BH, M_LAND), 256>>>(a2, scal, z0);

    // 6. Newton-Schulz iterations
    float* zc = z0;
    float* zn = z1;
    for (int it = 0; it < PINV_ITERS; it++) {
        {   EpiStd e{xz, SZ2, M_LAND, 1.f, 0.f, nullptr, 0, nullptr};
            gemm_tf32<128, 128, 64, 32, EpiStd><<<dim3(2, 2, N_BH), 256>>>(
                a2, SZ2, M_LAND, zc, SZ2, M_LAND, M_LAND, e); }
        {   EpiStd e{w2, SZ2, M_LAND, -1.f, 7.f, xz, SZ2, nullptr};
            gemm_tf32<128, 128, 64, 32, EpiStd><<<dim3(2, 2, N_BH), 256>>>(
                xz, SZ2, M_LAND, xz, SZ2, M_LAND, M_LAND, e); }
        {   EpiStd e{w3, SZ2, M_LAND, -1.f, 15.f, xz, SZ2, nullptr};
            gemm_tf32<128, 128, 64, 32, EpiStd><<<dim3(2, 2, N_BH), 256>>>(
                xz, SZ2, M_LAND, w2, SZ2, M_LAND, M_LAND, e); }
        {   EpiStd e{zn, SZ2, M_LAND, -0.25f, 3.25f, zc, SZ2, nullptr};
            gemm_tf32<128, 128, 64, 32, EpiStd><<<dim3(2, 2, N_BH), 256>>>(
                zc, SZ2, M_LAND, w3, SZ2, M_LAND, M_LAND, e); }
        float* tswap = zc; zc = zn; zn = tswap;
    }

    // 7. flash A: a3v = softmax(ql @ k^T) @ v   [bh, 256, 64]
    flash_kernel<64, 128, 4, 0><<<dim3(M_LAND / 64, N_BH), 128, FLASH_SMEM>>>(
        ql, k, v, a3v, N_SEQ, M_LAND);

    // 8. zv = z_final @ a3v  [bh, 256, 64]
    {
        EpiStd e{zv, (size_t)M_LAND * D_HEAD, D_HEAD, 1.f, 0.f, nullptr, 0, nullptr};
        gemm_tf32<64, 64, 32, 16, EpiStd><<<dim3(1, M_LAND / 64, N_BH), 256>>>(
            zc, SZ2, M_LAND, a3v, (size_t)M_LAND * D_HEAD, D_HEAD, M_LAND, e);
    }

    // 9. flash B: outt = softmax(q @ kl^T) @ zv, written in [b,n,h*dh] layout
    flash_kernel<64, 128, 4, 1><<<dim3(N_SEQ / 64, N_BH), 128, FLASH_SMEM>>>(
        q, kl, zv, outt, M_LAND, N_SEQ);

    // 10. depthwise conv residual (adds into outt)
    conv_res_kernel<<<dim3(N_BH, N_SEQ / 64), 256>>>(v, res_w, outt);

    // 11. final GEMM: out = x + outt @ w_out + b_out
    {
        EpiStd e{out, 0, D_MODEL, 1.f, 1.f, x, 0, b_out};
        gemm_tf32<128, 128, 64, 32, EpiStd><<<dim3(D_MODEL / 128, N_ROWS / 128, 1), 256>>>(
            outt, 0, D_MODEL, w_out, 0, D_MODEL, D_MODEL, e);
    }
}

// ---------------- transpose [R,64] -> [64,R], batched (for kl only) ----------------
__global__ void transpose64_kernel(const float* __restrict__ src,
                                   float* __restrict__ dst, int R)
{
    __shared__ float tile[32][33];
    int z = blockIdx.z;
    int r0 = blockIdx.x * 32, c0 = blockIdx.y * 32;
    const float* s = src + (size_t)z * R * 64;
    float* d = dst + (size_t)z * 64 * R;
    tile[threadIdx.y][threadIdx.x] = s[(size_t)(r0 + threadIdx.y) * 64 + c0 + threadIdx.x];
    __syncthreads();
    d[(size_t)(c0 + threadIdx.y) * R + r0 + threadIdx.x] = tile[threadIdx.x][threadIdx.y];
}